// round 13
// baseline (speedup 1.0000x reference)
#include <cuda_runtime.h>
#include <cstdint>
#include <math.h>

#define BATCH   4
#define SEQ     2048
#define DMODEL  1024
#define DINNER  2048
#define DSTATE  64
#define MROWS   (BATCH*SEQ)      /* 8192 */
#define NPROJ   (2*DSTATE+1)     /* 129  */
#define NCH     16               /* scan chunks */
#define CHLEN   (SEQ/NCH)        /* 128 */

// ---------------- scratch (device globals; no allocations allowed) ----------
__device__ float g_xi  [MROWS*DINNER];
__device__ float g_sz  [MROWS*DINNER];
__device__ float g_bx  [MROWS*DINNER];
__device__ float g_y   [MROWS*DINNER];
__device__ float g_pBC [MROWS*128];
__device__ float g_dsum[MROWS];
__device__ float g_a   [MROWS];
__device__ float g_hend [BATCH*NCH*DINNER];
__device__ float g_carry[BATCH*NCH*DINNER];
__device__ float g_prodA[BATCH*NCH];
__device__ float g_xr  [MROWS*DMODEL];      // rounded x
__device__ float g_Wr  [DMODEL*2*DINNER];   // rounded W_in
__device__ float g_Wor [DINNER*DMODEL];     // rounded W_out
__device__ uint32_t g_WxhP[(DINNER/2)*128]; // W_xp[:,1:] k-pair bf16x2 hi
__device__ uint32_t g_WxlP[(DINNER/2)*128]; //                          lo
__device__ uint32_t g_WBhP[(DSTATE/2)*DINNER];
__device__ uint32_t g_WBlP[(DSTATE/2)*DINNER];
__device__ uint32_t g_WChP[(DSTATE/2)*DINNER];
__device__ uint32_t g_WClP[(DSTATE/2)*DINNER];

// ---------------- helpers ---------------------------------------------------
__device__ __forceinline__ uint32_t smem_u32(const void* p) {
    uint32_t a;
    asm("{ .reg .u64 t; cvta.to.shared.u64 t, %1; cvt.u32.u64 %0, t; }" : "=r"(a) : "l"(p));
    return a;
}
__device__ __forceinline__ float tf32r(float x) {
    float y; asm("cvt.rna.tf32.f32 %0, %1;" : "=f"(y) : "f"(x)); return y;
}
__device__ __forceinline__ uint32_t pkbf(float lo, float hi) {
    uint32_t r; asm("cvt.rn.bf16x2.f32 %0, %1, %2;" : "=r"(r) : "f"(hi), "f"(lo)); return r;
}
__device__ __forceinline__ float bflo(uint32_t p) { return __uint_as_float(p << 16); }
__device__ __forceinline__ float bfhi(uint32_t p) { return __uint_as_float(p & 0xFFFF0000u); }

__device__ __forceinline__ void cp16(uint32_t s, const void* g) {
    asm volatile("cp.async.cg.shared.global [%0], [%1], 16;" :: "r"(s), "l"(g));
}
#define CP_COMMIT asm volatile("cp.async.commit_group;" ::: "memory")
#define CP_WAIT1  asm volatile("cp.async.wait_group 1;" ::: "memory")
#define CP_WAIT0  asm volatile("cp.async.wait_group 0;" ::: "memory")

__device__ __forceinline__ void mma8(float* c, const uint32_t* a, const uint32_t* b) {
    asm volatile(
        "mma.sync.aligned.m16n8k8.row.col.f32.tf32.tf32.f32 "
        "{%0,%1,%2,%3}, {%4,%5,%6,%7}, {%8,%9}, {%0,%1,%2,%3};"
        : "+f"(c[0]), "+f"(c[1]), "+f"(c[2]), "+f"(c[3])
        : "r"(a[0]), "r"(a[1]), "r"(a[2]), "r"(a[3]), "r"(b[0]), "r"(b[1]));
}
__device__ __forceinline__ void mmabf(float* c, const uint32_t* a, const uint32_t* b) {
    asm volatile(
        "mma.sync.aligned.m16n8k16.row.col.f32.bf16.bf16.f32 "
        "{%0,%1,%2,%3}, {%4,%5,%6,%7}, {%8,%9}, {%0,%1,%2,%3};"
        : "+f"(c[0]), "+f"(c[1]), "+f"(c[2]), "+f"(c[3])
        : "r"(a[0]), "r"(a[1]), "r"(a[2]), "r"(a[3]), "r"(b[0]), "r"(b[1]));
}

// ---------------- prep kernels (separate launches, 903-style) ---------------
__global__ __launch_bounds__(256)
void round_kernel(const float* __restrict__ src, float* __restrict__ dst, int n4)
{
    int i = blockIdx.x * 256 + threadIdx.x;
    if (i < n4) {
        float4 v = reinterpret_cast<const float4*>(src)[i];
        v.x = tf32r(v.x); v.y = tf32r(v.y); v.z = tf32r(v.z); v.w = tf32r(v.w);
        reinterpret_cast<float4*>(dst)[i] = v;
    }
}

// W_B / W_C -> k-pair bf16x2 hi/lo [DSTATE/2][DINNER]
__global__ __launch_bounds__(256)
void packW_kernel(const float* __restrict__ src, uint32_t* __restrict__ dh,
                  uint32_t* __restrict__ dl)
{
    int i = blockIdx.x * 256 + threadIdx.x;
    int kp = i >> 11, n = i & 2047;
    float v0 = src[(size_t)(2 * kp) * DINNER + n];
    float v1 = src[(size_t)(2 * kp + 1) * DINNER + n];
    uint32_t h = pkbf(v0, v1);
    dh[i] = h;
    dl[i] = pkbf(v0 - bflo(h), v1 - bfhi(h));
}

// W_xp[:,1:129] -> k-pair bf16x2 hi/lo [DINNER/2][128]
__global__ __launch_bounds__(256)
void packxp_kernel(const float* __restrict__ W)
{
    int i = blockIdx.x * 256 + threadIdx.x;
    int kp = i >> 7, n = i & 127;
    float v0 = W[(size_t)(2 * kp) * NPROJ + 1 + n];
    float v1 = W[(size_t)(2 * kp + 1) * NPROJ + 1 + n];
    uint32_t h = pkbf(v0, v1);
    g_WxhP[i] = h;
    g_WxlP[i] = pkbf(v0 - bflo(h), v1 - bfhi(h));
}

// ======================= tf32 mma.sync GEMM, cp.async 3-stage ===============
// A and B both pre-rounded to tf32 (NO cvt in mainloop). Single sync per iter.
// MODE 0: C0=v   MODE 1: split xi / silu(z), fused delta dot into g_dsum
#define STG_SZ  35840u     /* 18432 A + 17408 B per stage */
#define GEMM_SMEM 107520   /* 3 stages */

template <int MODE>
__global__ void __launch_bounds__(256, 2)
gemm_cp(const float* __restrict__ A, int lda,
        const float* __restrict__ B, int ldb,
        float* __restrict__ C0, float* __restrict__ C1,
        const float* __restrict__ wxp,
        int N, int K)
{
    extern __shared__ char smem[];
    const uint32_t sbase = smem_u32(smem);
    float* fs = (float*)smem;

    const int t    = threadIdx.x;
    const int lane = t & 31;
    const int wid  = t >> 5;
    const int warpM = wid & 3;
    const int warpN = wid >> 2;

    int bx = blockIdx.x, by = blockIdx.y;
    {
        int lin = by * gridDim.x + bx;
        int per = gridDim.x * 8;
        int p = lin / per, rem = lin % per;
        by = p * 8 + (rem & 7);
        bx = rem >> 3;
    }
    const int rowBase = by * 128;
    const int colBase = bx * 128;

    float acc[2][8][4];
#pragma unroll
    for (int i = 0; i < 2; i++)
#pragma unroll
        for (int j = 0; j < 8; j++)
#pragma unroll
            for (int q = 0; q < 4; q++) acc[i][j][q] = 0.0f;

    const int nkt = K / 32;

    auto issue = [&](int st, int kt) {
        const int k0 = kt * 32;
        const uint32_t sA = sbase + (uint32_t)st * STG_SZ;
        const uint32_t sB = sA + 18432u;
#pragma unroll
        for (int e = 0; e < 4; e++) {
            int id = t + 256 * e;
            int r = id >> 3, q = id & 7;
            cp16(sA + (uint32_t)(r * 36 + q * 4) * 4,
                 A + (size_t)(rowBase + r) * lda + k0 + q * 4);
        }
#pragma unroll
        for (int e = 0; e < 4; e++) {
            int id = t + 256 * e;
            int k = id >> 5, q = id & 31;
            cp16(sB + (uint32_t)(k * 136 + q * 4) * 4,
                 B + (size_t)(k0 + k) * ldb + colBase + q * 4);
        }
    };

    issue(0, 0);
    CP_COMMIT;
    if (nkt > 1) { issue(1, 1); CP_COMMIT; }

    const int r0 = warpM * 32 + (lane >> 2);
    const int kq = lane & 3;
    const int cl = warpN * 64 + (lane >> 2);

    for (int kt = 0; kt < nkt; kt++) {
        if (kt + 1 < nkt) CP_WAIT1; else CP_WAIT0;
        __syncthreads();
        if (kt + 2 < nkt) { issue((kt + 2) % 3, kt + 2); CP_COMMIT; }

        const uint32_t aS = (uint32_t)(kt % 3) * (STG_SZ / 4);
        const uint32_t bS = aS + 18432 / 4;
#pragma unroll
        for (int ks = 0; ks < 4; ks++) {
            const int kb = ks * 8;
            uint32_t af[2][4];
#pragma unroll
            for (int mt = 0; mt < 2; mt++) {
                int rr = r0 + mt * 16;
                af[mt][0] = __float_as_uint(fs[aS + (rr    ) * 36 + kb + kq]);
                af[mt][1] = __float_as_uint(fs[aS + (rr + 8) * 36 + kb + kq]);
                af[mt][2] = __float_as_uint(fs[aS + (rr    ) * 36 + kb + kq + 4]);
                af[mt][3] = __float_as_uint(fs[aS + (rr + 8) * 36 + kb + kq + 4]);
            }
#pragma unroll
            for (int nt = 0; nt < 8; nt++) {
                int cc = cl + nt * 8;
                uint32_t bf[2] = {
                    __float_as_uint(fs[bS + (kb + kq    ) * 136 + cc]),
                    __float_as_uint(fs[bS + (kb + kq + 4) * 136 + cc]) };
#pragma unroll
                for (int mt = 0; mt < 2; mt++)
                    mma8(acc[mt][nt], af[mt], bf);
            }
        }
    }

    // ---- epilogue
    float* C = C0;
    int cbase = colBase;
    bool do_silu = false;
    int cstride = N;
    if (MODE == 1) {
        cstride = DINNER;
        if (colBase >= DINNER) { C = C1; cbase = colBase - DINNER; do_silu = true; }
    }

    float ds[4] = {0.0f, 0.0f, 0.0f, 0.0f};

#pragma unroll
    for (int mt = 0; mt < 2; mt++) {
#pragma unroll
        for (int nt = 0; nt < 8; nt++) {
            int gr = rowBase + warpM * 32 + mt * 16 + (lane >> 2);
            int gc = cbase + warpN * 64 + nt * 8 + 2 * (lane & 3);
            float w0a = 0.0f, w0b = 0.0f;
            if (MODE == 1 && !do_silu) {
                w0a = __ldg(&wxp[(size_t)gc * NPROJ]);
                w0b = __ldg(&wxp[(size_t)(gc + 1) * NPROJ]);
            }
#pragma unroll
            for (int h = 0; h < 2; h++) {
                float v0 = acc[mt][nt][2 * h];
                float v1 = acc[mt][nt][2 * h + 1];
                int r = gr + h * 8;
                if (MODE == 1) {
                    if (do_silu) {
                        v0 = v0 / (1.0f + expf(-v0));
                        v1 = v1 / (1.0f + expf(-v1));
                    } else {
                        ds[mt * 2 + h] += v0 * w0a + v1 * w0b;
                    }
                }
                float2 o; o.x = v0; o.y = v1;
                *reinterpret_cast<float2*>(C + (size_t)r * cstride + gc) = o;
            }
        }
    }

    if (MODE == 1 && !do_silu) {
#pragma unroll
        for (int i = 0; i < 4; i++) {
            float v = ds[i];
            v += __shfl_xor_sync(0xFFFFFFFFu, v, 1);
            v += __shfl_xor_sync(0xFFFFFFFFu, v, 2);
            if ((lane & 3) == 0) {
                int r = rowBase + warpM * 32 + (i >> 1) * 16 + (i & 1) * 8 + (lane >> 2);
                atomicAdd(&g_dsum[r], v);
            }
        }
    }
}

// ============ 2-term bf16 split GEMM (m16n8k16), prebuilt hi/lo B ===========
// 3 MMAs per K=16: ah*bh + ah*bl + al*bh  (al*bl ~ 2^-18, dropped).
// MODE 0: no direct store (FUSE=2 path)  MODE 2: C0=v*aux  MODE 3: atomicAdd
// FUSE 0: none
// FUSE 1: (bx GEMM) stage tile, chunk-local scan -> g_hend  (tile rows == chunk)
// FUSE 2: (Cm GEMM) stage tile, re-scan with carry, write y; Cm never hits gmem
#define BF_STG  37888u     /* 20480 A + 8704 Bh + 8704 Bl */
#define BF_SMEM 75776

template <int MODE, int FUSE>
__global__ void __launch_bounds__(256, 2)
gemm_bf(const float* __restrict__ A, int lda,
        const uint32_t* __restrict__ Bh, const uint32_t* __restrict__ Bl, int ldbp,
        float* __restrict__ C0, const float* __restrict__ aux,
        const float* __restrict__ Dv,
        int N, int K)
{
    extern __shared__ char smem[];
    const uint32_t sbase = smem_u32(smem);
    float* fs = (float*)smem;
    uint32_t* us = (uint32_t*)smem;

    const int t    = threadIdx.x;
    const int lane = t & 31;
    const int wid  = t >> 5;
    const int warpM = wid & 3;
    const int warpN = wid >> 2;
    const int rowBase = blockIdx.y * 128;
    const int colBase = blockIdx.x * 128;
    const int kBase   = blockIdx.z * K;

    float acc[2][8][4];
#pragma unroll
    for (int i = 0; i < 2; i++)
#pragma unroll
        for (int j = 0; j < 8; j++)
#pragma unroll
            for (int q = 0; q < 4; q++) acc[i][j][q] = 0.0f;

    const int nkt = K / 32;

    auto issue = [&](int st, int kt) {
        const int k0  = kBase + kt * 32;
        const int k0p = k0 >> 1;
        const uint32_t sA  = sbase + (uint32_t)st * BF_STG;
        const uint32_t sBh = sA + 20480u;
        const uint32_t sBl = sBh + 8704u;
#pragma unroll
        for (int e = 0; e < 4; e++) {
            int id = t + 256 * e;
            int r = id >> 3, q = id & 7;
            cp16(sA + (uint32_t)(r * 40 + q * 4) * 4,
                 A + (size_t)(rowBase + r) * lda + k0 + q * 4);
        }
#pragma unroll
        for (int e = 0; e < 2; e++) {
            int id = t + 256 * e;
            int kp = id >> 5, q = id & 31;
            cp16(sBh + (uint32_t)(kp * 136 + q * 4) * 4,
                 Bh + (size_t)(k0p + kp) * ldbp + colBase + q * 4);
            cp16(sBl + (uint32_t)(kp * 136 + q * 4) * 4,
                 Bl + (size_t)(k0p + kp) * ldbp + colBase + q * 4);
        }
    };

    issue(0, 0);
    CP_COMMIT;

    const int r0 = warpM * 32 + (lane >> 2);
    const int kq = lane & 3;
    const int cl = warpN * 64 + (lane >> 2);

    for (int kt = 0; kt < nkt; kt++) {
        if (kt + 1 < nkt) { issue((kt + 1) & 1, kt + 1); CP_COMMIT; CP_WAIT1; }
        else              { CP_WAIT0; }
        __syncthreads();

        const uint32_t aS  = (uint32_t)(kt & 1) * (BF_STG / 4);
        const uint32_t bhS = aS + 20480 / 4;
        const uint32_t blS = bhS + 8704 / 4;
#pragma unroll
        for (int ks = 0; ks < 2; ks++) {
            const int kb = ks * 16;
            uint32_t ah[2][4], al[2][4];
#pragma unroll
            for (int mt = 0; mt < 2; mt++) {
                int rr = r0 + mt * 16;
                float2 p0 = *(const float2*)&fs[aS + (rr    ) * 40 + kb + 2 * kq];
                float2 p1 = *(const float2*)&fs[aS + (rr + 8) * 40 + kb + 2 * kq];
                float2 p2 = *(const float2*)&fs[aS + (rr    ) * 40 + kb + 2 * kq + 8];
                float2 p3 = *(const float2*)&fs[aS + (rr + 8) * 40 + kb + 2 * kq + 8];
                ah[mt][0] = pkbf(p0.x, p0.y);
                ah[mt][1] = pkbf(p1.x, p1.y);
                ah[mt][2] = pkbf(p2.x, p2.y);
                ah[mt][3] = pkbf(p3.x, p3.y);
                al[mt][0] = pkbf(p0.x - bflo(ah[mt][0]), p0.y - bfhi(ah[mt][0]));
                al[mt][1] = pkbf(p1.x - bflo(ah[mt][1]), p1.y - bfhi(ah[mt][1]));
                al[mt][2] = pkbf(p2.x - bflo(ah[mt][2]), p2.y - bfhi(ah[mt][2]));
                al[mt][3] = pkbf(p3.x - bflo(ah[mt][3]), p3.y - bfhi(ah[mt][3]));
            }
#pragma unroll
            for (int nt = 0; nt < 8; nt++) {
                int cc = cl + nt * 8;
                uint32_t bh2[2] = { us[bhS + (ks * 8 + kq    ) * 136 + cc],
                                    us[bhS + (ks * 8 + kq + 4) * 136 + cc] };
                uint32_t bl2[2] = { us[blS + (ks * 8 + kq    ) * 136 + cc],
                                    us[blS + (ks * 8 + kq + 4) * 136 + cc] };
#pragma unroll
                for (int mt = 0; mt < 2; mt++) {
                    mmabf(acc[mt][nt], ah[mt], bl2);
                    mmabf(acc[mt][nt], al[mt], bh2);
                    mmabf(acc[mt][nt], ah[mt], bh2);
                }
            }
        }
        __syncthreads();
    }

    // ---- epilogue (pipeline smem is dead now; reuse for stage + a-vector)
    float* stg = fs;            // [128][132]  = 67584 B
    float* sav = fs + 16896;    // [128]       -> total 68096 B <= 75776

    if (FUSE) {
        if (t < 128) sav[t] = g_a[rowBase + t];
    }

#pragma unroll
    for (int mt = 0; mt < 2; mt++) {
#pragma unroll
        for (int nt = 0; nt < 8; nt++) {
            int rt = warpM * 32 + mt * 16 + (lane >> 2);
            int ct = warpN * 64 + nt * 8 + 2 * (lane & 3);
            int gr = rowBase + rt;
            int gc = colBase + ct;
#pragma unroll
            for (int h = 0; h < 2; h++) {
                float v0 = acc[mt][nt][2 * h];
                float v1 = acc[mt][nt][2 * h + 1];
                int r = gr + h * 8;
                if (MODE == 2) {
                    float2 a2 = *reinterpret_cast<const float2*>(aux + (size_t)r * N + gc);
                    v0 *= a2.x; v1 *= a2.y;
                }
                if (FUSE) {
                    stg[(rt + h * 8) * 132 + ct]     = v0;
                    stg[(rt + h * 8) * 132 + ct + 1] = v1;
                }
                if (MODE == 3) {
                    atomicAdd(C0 + (size_t)r * N + gc,     v0);
                    atomicAdd(C0 + (size_t)r * N + gc + 1, v1);
                } else if (FUSE != 2) {
                    float2 o; o.x = v0; o.y = v1;
                    *reinterpret_cast<float2*>(C0 + (size_t)r * N + gc) = o;
                }
            }
        }
    }

    if (FUSE) {
        __syncthreads();
        if (t < 128) {
            if (FUSE == 1) {
                // chunk-local scan -> hend  (chunk id == blockIdx.y)
                float h = 0.0f;
#pragma unroll 4
                for (int i = 0; i < CHLEN; i++)
                    h = fmaf(sav[i], h, stg[i * 132 + t]);
                g_hend[(size_t)blockIdx.y * DINNER + colBase + t] = h;
            } else {
                // re-scan with carry + y = tf32((Cm*h + D*xi)*sz)
                int d = colBase + t;
                float h = g_carry[(size_t)blockIdx.y * DINNER + d];
                float Dd = Dv[d];
                size_t base = (size_t)rowBase * DINNER + d;
#pragma unroll 4
                for (int i = 0; i < CHLEN; i++) {
                    size_t idx = base + (size_t)i * DINNER;
                    float bx = g_bx[idx];
                    float xi = g_xi[idx];
                    float sz = g_sz[idx];
                    h = fmaf(sav[i], h, bx);
                    float y = fmaf(stg[i * 132 + t], h, Dd * xi);
                    g_y[idx] = tf32r(y * sz);
                }
            }
        }
    }
}

// ---------------- softplus -> A_bar -----------------------------------------
__global__ __launch_bounds__(256)
void softplus_kernel(const float* __restrict__ A_log)
{
    int m = blockIdx.x * 256 + threadIdx.x;
    float v = g_dsum[m];
    float sp = (v > 20.0f) ? v : log1pf(expf(v));
    g_a[m] = expf(-expf(A_log[0]) * sp);
}

// ---------------- chunk products --------------------------------------------
__global__ __launch_bounds__(128)
void prod_kernel()
{
    float v = g_a[blockIdx.x * 128 + threadIdx.x];
#pragma unroll
    for (int o = 16; o; o >>= 1) v *= __shfl_xor_sync(0xFFFFFFFFu, v, o);
    __shared__ float red[4];
    if ((threadIdx.x & 31) == 0) red[threadIdx.x >> 5] = v;
    __syncthreads();
    if (threadIdx.x == 0)
        g_prodA[blockIdx.x] = red[0] * red[1] * red[2] * red[3];
}

// ---------------- carries across chunks -------------------------------------
__global__ __launch_bounds__(256)
void scanB_kernel()
{
    int b = blockIdx.x >> 3;
    int d = (blockIdx.x & 7) * 256 + threadIdx.x;
    float carry = 0.0f;
#pragma unroll
    for (int c = 0; c < NCH; c++) {
        size_t idx = (size_t)(b * NCH + c) * DINNER + d;
        g_carry[idx] = carry;
        carry = g_hend[idx] + g_prodA[b * NCH + c] * carry;
    }
}

// ---------------- launch ----------------------------------------------------
extern "C" void kernel_launch(void* const* d_in, const int* in_sizes, int n_in,
                              void* d_out, int out_size)
{
    const float* x     = (const float*)d_in[0];
    const float* W_in  = (const float*)d_in[1];
    const float* W_xp  = (const float*)d_in[2];
    const float* W_B   = (const float*)d_in[3];
    const float* W_C   = (const float*)d_in[4];
    const float* W_out = (const float*)d_in[5];
    const float* Dvec  = (const float*)d_in[6];
    const float* A_log = (const float*)d_in[7];
    float* out = (float*)d_out;

    float *p_xi, *p_sz, *p_bx, *p_y, *p_pBC, *p_dsum, *p_xr, *p_Wr, *p_Wor;
    uint32_t *p_WxhP, *p_WxlP, *p_WBhP, *p_WBlP, *p_WChP, *p_WClP;
    cudaGetSymbolAddress((void**)&p_xi,   g_xi);
    cudaGetSymbolAddress((void**)&p_sz,   g_sz);
    cudaGetSymbolAddress((void**)&p_bx,   g_bx);
    cudaGetSymbolAddress((void**)&p_y,    g_y);
    cudaGetSymbolAddress((void**)&p_pBC,  g_pBC);
    cudaGetSymbolAddress((void**)&p_dsum, g_dsum);
    cudaGetSymbolAddress((void**)&p_xr,   g_xr);
    cudaGetSymbolAddress((void**)&p_Wr,   g_Wr);
    cudaGetSymbolAddress((void**)&p_Wor,  g_Wor);
    cudaGetSymbolAddress((void**)&p_WxhP, g_WxhP);
    cudaGetSymbolAddress((void**)&p_WxlP, g_WxlP);
    cudaGetSymbolAddress((void**)&p_WBhP, g_WBhP);
    cudaGetSymbolAddress((void**)&p_WBlP, g_WBlP);
    cudaGetSymbolAddress((void**)&p_WChP, g_WChP);
    cudaGetSymbolAddress((void**)&p_WClP, g_WClP);

    cudaFuncSetAttribute(gemm_cp<0>, cudaFuncAttributeMaxDynamicSharedMemorySize, GEMM_SMEM);
    cudaFuncSetAttribute(gemm_cp<1>, cudaFuncAttributeMaxDynamicSharedMemorySize, GEMM_SMEM);
    cudaFuncSetAttribute(gemm_bf<3,0>, cudaFuncAttributeMaxDynamicSharedMemorySize, BF_SMEM);
    cudaFuncSetAttribute(gemm_bf<2,1>, cudaFuncAttributeMaxDynamicSharedMemorySize, BF_SMEM);
    cudaFuncSetAttribute(gemm_bf<0,2>, cudaFuncAttributeMaxDynamicSharedMemorySize, BF_SMEM);

    // 0) prep: separate small launches + memsets
    round_kernel<<<MROWS * DMODEL / 1024, 256>>>(x, p_xr, MROWS * DMODEL / 4);
    round_kernel<<<DMODEL * 2 * DINNER / 1024, 256>>>(W_in,  p_Wr,  DMODEL * 2 * DINNER / 4);
    round_kernel<<<DINNER * DMODEL / 1024, 256>>>(W_out, p_Wor, DINNER * DMODEL / 4);
    packW_kernel<<<(DSTATE / 2) * DINNER / 256, 256>>>(W_B, p_WBhP, p_WBlP);
    packW_kernel<<<(DSTATE / 2) * DINNER / 256, 256>>>(W_C, p_WChP, p_WClP);
    packxp_kernel<<<(DINNER / 2) * 128 / 256, 256>>>(W_xp);
    cudaMemsetAsync(p_pBC,  0, (size_t)MROWS * 128 * sizeof(float), 0);
    cudaMemsetAsync(p_dsum, 0, (size_t)MROWS * sizeof(float), 0);

    // 1) xz = x @ W_in -> xi, silu(z); fused delta dot -> g_dsum
    gemm_cp<1><<<dim3(32, 64), 256, GEMM_SMEM>>>(
        p_xr, DMODEL, p_Wr, 2 * DINNER, p_xi, p_sz, W_xp, 2 * DINNER, DMODEL);

    // 2) softplus -> A_bar; chunk products
    softplus_kernel<<<MROWS / 256, 256>>>(A_log);
    prod_kernel<<<BATCH * NCH, 128>>>();

    // 3) [B_raw|C_raw] = xi @ W_xp[:,1:129]  (split-K x8, 2-term bf16)
    gemm_bf<3,0><<<dim3(1, 64, 8), 256, BF_SMEM>>>(
        p_xi, DINNER, p_WxhP, p_WxlP, 128, p_pBC, nullptr, nullptr, 128, DINNER / 8);

    // 4) bx = (B_raw @ W_B) * xi  + fused chunk-local scan -> hend
    gemm_bf<2,1><<<dim3(16, 64), 256, BF_SMEM>>>(
        p_pBC, 128, p_WBhP, p_WBlP, DINNER, p_bx, p_xi, nullptr, DINNER, DSTATE);

    // 5) carries across chunks
    scanB_kernel<<<BATCH * (DINNER / 256), 256>>>();

    // 6) Cm = C_raw @ W_C  + fused re-scan -> y   (Cm never written to gmem)
    gemm_bf<0,2><<<dim3(16, 64), 256, BF_SMEM>>>(
        p_pBC + 64, 128, p_WChP, p_WClP, DINNER, nullptr, nullptr, Dvec, DINNER, DSTATE);

    // 7) out = y @ W_out
    gemm_cp<0><<<dim3(8, 64), 256, GEMM_SMEM>>>(
        p_y, DINNER, p_Wor, DMODEL, out, nullptr, nullptr, DMODEL, DINNER);
}

// round 14
// speedup vs baseline: 1.2336x; 1.2336x over previous
#include <cuda_runtime.h>
#include <cstdint>
#include <math.h>

#define BATCH   4
#define SEQ     2048
#define DMODEL  1024
#define DINNER  2048
#define DSTATE  64
#define MROWS   (BATCH*SEQ)      /* 8192 */
#define NPROJ   (2*DSTATE+1)     /* 129  */
#define NCH     16               /* scan chunks */
#define CHLEN   (SEQ/NCH)        /* 128 */

// ---------------- scratch (device globals; no allocations allowed) ----------
__device__ float g_xi  [MROWS*DINNER];
__device__ float g_sz  [MROWS*DINNER];
__device__ float g_bx  [MROWS*DINNER];
__device__ float g_Cm  [MROWS*DINNER];
__device__ float g_y   [MROWS*DINNER];
__device__ float g_pBC [MROWS*128];
__device__ float g_dsum[MROWS];
__device__ float g_a   [MROWS];
__device__ float g_hend [BATCH*NCH*DINNER];
__device__ float g_carry[BATCH*NCH*DINNER];
__device__ float g_prodA[BATCH*NCH];
__device__ float g_xr  [MROWS*DMODEL];      // rounded x
__device__ float g_Wr  [DMODEL*2*DINNER];   // rounded W_in
__device__ float g_Wor [DINNER*DMODEL];     // rounded W_out
__device__ uint32_t g_WxhP[(DINNER/2)*128]; // W_xp[:,1:] k-pair bf16x2 hi
__device__ uint32_t g_WxlP[(DINNER/2)*128]; //                          lo
__device__ uint32_t g_WBhP[(DSTATE/2)*DINNER];
__device__ uint32_t g_WBlP[(DSTATE/2)*DINNER];
__device__ uint32_t g_WChP[(DSTATE/2)*DINNER];
__device__ uint32_t g_WClP[(DSTATE/2)*DINNER];

// ---------------- helpers ---------------------------------------------------
__device__ __forceinline__ uint32_t smem_u32(const void* p) {
    uint32_t a;
    asm("{ .reg .u64 t; cvta.to.shared.u64 t, %1; cvt.u32.u64 %0, t; }" : "=r"(a) : "l"(p));
    return a;
}
__device__ __forceinline__ float tf32r(float x) {
    float y; asm("cvt.rna.tf32.f32 %0, %1;" : "=f"(y) : "f"(x)); return y;
}
__device__ __forceinline__ uint32_t pkbf(float lo, float hi) {
    uint32_t r; asm("cvt.rn.bf16x2.f32 %0, %1, %2;" : "=r"(r) : "f"(hi), "f"(lo)); return r;
}
__device__ __forceinline__ float bflo(uint32_t p) { return __uint_as_float(p << 16); }
__device__ __forceinline__ float bfhi(uint32_t p) { return __uint_as_float(p & 0xFFFF0000u); }

__device__ __forceinline__ void cp16(uint32_t s, const void* g) {
    asm volatile("cp.async.cg.shared.global [%0], [%1], 16;" :: "r"(s), "l"(g));
}
#define CP_COMMIT asm volatile("cp.async.commit_group;" ::: "memory")
#define CP_WAIT1  asm volatile("cp.async.wait_group 1;" ::: "memory")
#define CP_WAIT0  asm volatile("cp.async.wait_group 0;" ::: "memory")

__device__ __forceinline__ void mma8(float* c, const uint32_t* a, const uint32_t* b) {
    asm volatile(
        "mma.sync.aligned.m16n8k8.row.col.f32.tf32.tf32.f32 "
        "{%0,%1,%2,%3}, {%4,%5,%6,%7}, {%8,%9}, {%0,%1,%2,%3};"
        : "+f"(c[0]), "+f"(c[1]), "+f"(c[2]), "+f"(c[3])
        : "r"(a[0]), "r"(a[1]), "r"(a[2]), "r"(a[3]), "r"(b[0]), "r"(b[1]));
}
__device__ __forceinline__ void mmabf(float* c, const uint32_t* a, const uint32_t* b) {
    asm volatile(
        "mma.sync.aligned.m16n8k16.row.col.f32.bf16.bf16.f32 "
        "{%0,%1,%2,%3}, {%4,%5,%6,%7}, {%8,%9}, {%0,%1,%2,%3};"
        : "+f"(c[0]), "+f"(c[1]), "+f"(c[2]), "+f"(c[3])
        : "r"(a[0]), "r"(a[1]), "r"(a[2]), "r"(a[3]), "r"(b[0]), "r"(b[1]));
}

// ---------------- prep kernels ----------------------------------------------
__global__ __launch_bounds__(256)
void round_kernel(const float* __restrict__ src, float* __restrict__ dst, int n4)
{
    int i = blockIdx.x * 256 + threadIdx.x;
    if (i < n4) {
        float4 v = reinterpret_cast<const float4*>(src)[i];
        v.x = tf32r(v.x); v.y = tf32r(v.y); v.z = tf32r(v.z); v.w = tf32r(v.w);
        reinterpret_cast<float4*>(dst)[i] = v;
    }
}

// W_B / W_C -> k-pair bf16x2 hi/lo [DSTATE/2][DINNER]
__global__ __launch_bounds__(256)
void packW_kernel(const float* __restrict__ src, uint32_t* __restrict__ dh,
                  uint32_t* __restrict__ dl)
{
    int i = blockIdx.x * 256 + threadIdx.x;
    int kp = i >> 11, n = i & 2047;
    float v0 = src[(size_t)(2 * kp) * DINNER + n];
    float v1 = src[(size_t)(2 * kp + 1) * DINNER + n];
    uint32_t h = pkbf(v0, v1);
    dh[i] = h;
    dl[i] = pkbf(v0 - bflo(h), v1 - bfhi(h));
}

// W_xp[:,1:129] -> k-pair bf16x2 hi/lo [DINNER/2][128]
__global__ __launch_bounds__(256)
void packxp_kernel(const float* __restrict__ W)
{
    int i = blockIdx.x * 256 + threadIdx.x;
    int kp = i >> 7, n = i & 127;
    float v0 = W[(size_t)(2 * kp) * NPROJ + 1 + n];
    float v1 = W[(size_t)(2 * kp + 1) * NPROJ + 1 + n];
    uint32_t h = pkbf(v0, v1);
    g_WxhP[i] = h;
    g_WxlP[i] = pkbf(v0 - bflo(h), v1 - bfhi(h));
}

// ======================= tf32 mma.sync GEMM, cp.async 3-stage ===============
// A and B both pre-rounded to tf32 (NO cvt in mainloop). Single sync per iter.
// MODE 0: C0=v   MODE 1: split xi / silu(z), fused delta dot into g_dsum
#define STG_SZ  35840u     /* 18432 A + 17408 B per stage */
#define GEMM_SMEM 107520   /* 3 stages */

template <int MODE>
__global__ void __launch_bounds__(256, 2)
gemm_cp(const float* __restrict__ A, int lda,
        const float* __restrict__ B, int ldb,
        float* __restrict__ C0, float* __restrict__ C1,
        const float* __restrict__ wxp,
        int N, int K)
{
    extern __shared__ char smem[];
    const uint32_t sbase = smem_u32(smem);
    float* fs = (float*)smem;

    const int t    = threadIdx.x;
    const int lane = t & 31;
    const int wid  = t >> 5;
    const int warpM = wid & 3;
    const int warpN = wid >> 2;

    int bx = blockIdx.x, by = blockIdx.y;
    {
        int lin = by * gridDim.x + bx;
        int per = gridDim.x * 8;
        int p = lin / per, rem = lin % per;
        by = p * 8 + (rem & 7);
        bx = rem >> 3;
    }
    const int rowBase = by * 128;
    const int colBase = bx * 128;

    float acc[2][8][4];
#pragma unroll
    for (int i = 0; i < 2; i++)
#pragma unroll
        for (int j = 0; j < 8; j++)
#pragma unroll
            for (int q = 0; q < 4; q++) acc[i][j][q] = 0.0f;

    const int nkt = K / 32;

    auto issue = [&](int st, int kt) {
        const int k0 = kt * 32;
        const uint32_t sA = sbase + (uint32_t)st * STG_SZ;
        const uint32_t sB = sA + 18432u;
#pragma unroll
        for (int e = 0; e < 4; e++) {
            int id = t + 256 * e;
            int r = id >> 3, q = id & 7;
            cp16(sA + (uint32_t)(r * 36 + q * 4) * 4,
                 A + (size_t)(rowBase + r) * lda + k0 + q * 4);
        }
#pragma unroll
        for (int e = 0; e < 4; e++) {
            int id = t + 256 * e;
            int k = id >> 5, q = id & 31;
            cp16(sB + (uint32_t)(k * 136 + q * 4) * 4,
                 B + (size_t)(k0 + k) * ldb + colBase + q * 4);
        }
    };

    issue(0, 0);
    CP_COMMIT;
    if (nkt > 1) { issue(1, 1); CP_COMMIT; }

    const int r0 = warpM * 32 + (lane >> 2);
    const int kq = lane & 3;
    const int cl = warpN * 64 + (lane >> 2);

    for (int kt = 0; kt < nkt; kt++) {
        if (kt + 1 < nkt) CP_WAIT1; else CP_WAIT0;
        __syncthreads();
        if (kt + 2 < nkt) { issue((kt + 2) % 3, kt + 2); CP_COMMIT; }

        const uint32_t aS = (uint32_t)(kt % 3) * (STG_SZ / 4);
        const uint32_t bS = aS + 18432 / 4;
#pragma unroll
        for (int ks = 0; ks < 4; ks++) {
            const int kb = ks * 8;
            uint32_t af[2][4];
#pragma unroll
            for (int mt = 0; mt < 2; mt++) {
                int rr = r0 + mt * 16;
                af[mt][0] = __float_as_uint(fs[aS + (rr    ) * 36 + kb + kq]);
                af[mt][1] = __float_as_uint(fs[aS + (rr + 8) * 36 + kb + kq]);
                af[mt][2] = __float_as_uint(fs[aS + (rr    ) * 36 + kb + kq + 4]);
                af[mt][3] = __float_as_uint(fs[aS + (rr + 8) * 36 + kb + kq + 4]);
            }
#pragma unroll
            for (int nt = 0; nt < 8; nt++) {
                int cc = cl + nt * 8;
                uint32_t bf[2] = {
                    __float_as_uint(fs[bS + (kb + kq    ) * 136 + cc]),
                    __float_as_uint(fs[bS + (kb + kq + 4) * 136 + cc]) };
#pragma unroll
                for (int mt = 0; mt < 2; mt++)
                    mma8(acc[mt][nt], af[mt], bf);
            }
        }
    }

    // ---- epilogue
    float* C = C0;
    int cbase = colBase;
    bool do_silu = false;
    int cstride = N;
    if (MODE == 1) {
        cstride = DINNER;
        if (colBase >= DINNER) { C = C1; cbase = colBase - DINNER; do_silu = true; }
    }

    float ds[4] = {0.0f, 0.0f, 0.0f, 0.0f};

#pragma unroll
    for (int mt = 0; mt < 2; mt++) {
#pragma unroll
        for (int nt = 0; nt < 8; nt++) {
            int gr = rowBase + warpM * 32 + mt * 16 + (lane >> 2);
            int gc = cbase + warpN * 64 + nt * 8 + 2 * (lane & 3);
            float w0a = 0.0f, w0b = 0.0f;
            if (MODE == 1 && !do_silu) {
                w0a = __ldg(&wxp[(size_t)gc * NPROJ]);
                w0b = __ldg(&wxp[(size_t)(gc + 1) * NPROJ]);
            }
#pragma unroll
            for (int h = 0; h < 2; h++) {
                float v0 = acc[mt][nt][2 * h];
                float v1 = acc[mt][nt][2 * h + 1];
                int r = gr + h * 8;
                if (MODE == 1) {
                    if (do_silu) {
                        v0 = v0 / (1.0f + expf(-v0));
                        v1 = v1 / (1.0f + expf(-v1));
                    } else {
                        ds[mt * 2 + h] += v0 * w0a + v1 * w0b;
                    }
                }
                float2 o; o.x = v0; o.y = v1;
                *reinterpret_cast<float2*>(C + (size_t)r * cstride + gc) = o;
            }
        }
    }

    if (MODE == 1 && !do_silu) {
#pragma unroll
        for (int i = 0; i < 4; i++) {
            float v = ds[i];
            v += __shfl_xor_sync(0xFFFFFFFFu, v, 1);
            v += __shfl_xor_sync(0xFFFFFFFFu, v, 2);
            if ((lane & 3) == 0) {
                int r = rowBase + warpM * 32 + (i >> 1) * 16 + (i & 1) * 8 + (lane >> 2);
                atomicAdd(&g_dsum[r], v);
            }
        }
    }
}

// ============ 2-term bf16 split GEMM (m16n8k16), prebuilt hi/lo B ===========
// 3 MMAs per K=16: ah*bh + ah*bl + al*bh  (al*bl ~ 2^-18, dropped).
// MODE 0: C0=v   MODE 2: C0=v*aux   MODE 3: atomicAdd (split-K)
#define BF_STG  37888u     /* 20480 A + 8704 Bh + 8704 Bl */
#define BF_SMEM 75776

template <int MODE>
__global__ void __launch_bounds__(256, 2)
gemm_bf(const float* __restrict__ A, int lda,
        const uint32_t* __restrict__ Bh, const uint32_t* __restrict__ Bl, int ldbp,
        float* __restrict__ C0, const float* __restrict__ aux,
        int N, int K)
{
    extern __shared__ char smem[];
    const uint32_t sbase = smem_u32(smem);
    float* fs = (float*)smem;
    uint32_t* us = (uint32_t*)smem;

    const int t    = threadIdx.x;
    const int lane = t & 31;
    const int wid  = t >> 5;
    const int warpM = wid & 3;
    const int warpN = wid >> 2;
    const int rowBase = blockIdx.y * 128;
    const int colBase = blockIdx.x * 128;
    const int kBase   = blockIdx.z * K;

    float acc[2][8][4];
#pragma unroll
    for (int i = 0; i < 2; i++)
#pragma unroll
        for (int j = 0; j < 8; j++)
#pragma unroll
            for (int q = 0; q < 4; q++) acc[i][j][q] = 0.0f;

    const int nkt = K / 32;

    auto issue = [&](int st, int kt) {
        const int k0  = kBase + kt * 32;
        const int k0p = k0 >> 1;
        const uint32_t sA  = sbase + (uint32_t)st * BF_STG;
        const uint32_t sBh = sA + 20480u;
        const uint32_t sBl = sBh + 8704u;
#pragma unroll
        for (int e = 0; e < 4; e++) {
            int id = t + 256 * e;
            int r = id >> 3, q = id & 7;
            cp16(sA + (uint32_t)(r * 40 + q * 4) * 4,
                 A + (size_t)(rowBase + r) * lda + k0 + q * 4);
        }
#pragma unroll
        for (int e = 0; e < 2; e++) {
            int id = t + 256 * e;
            int kp = id >> 5, q = id & 31;
            cp16(sBh + (uint32_t)(kp * 136 + q * 4) * 4,
                 Bh + (size_t)(k0p + kp) * ldbp + colBase + q * 4);
            cp16(sBl + (uint32_t)(kp * 136 + q * 4) * 4,
                 Bl + (size_t)(k0p + kp) * ldbp + colBase + q * 4);
        }
    };

    issue(0, 0);
    CP_COMMIT;

    const int r0 = warpM * 32 + (lane >> 2);
    const int kq = lane & 3;
    const int cl = warpN * 64 + (lane >> 2);

    for (int kt = 0; kt < nkt; kt++) {
        if (kt + 1 < nkt) { issue((kt + 1) & 1, kt + 1); CP_COMMIT; CP_WAIT1; }
        else              { CP_WAIT0; }
        __syncthreads();

        const uint32_t aS  = (uint32_t)(kt & 1) * (BF_STG / 4);
        const uint32_t bhS = aS + 20480 / 4;
        const uint32_t blS = bhS + 8704 / 4;
#pragma unroll
        for (int ks = 0; ks < 2; ks++) {
            const int kb = ks * 16;
            uint32_t ah[2][4], al[2][4];
#pragma unroll
            for (int mt = 0; mt < 2; mt++) {
                int rr = r0 + mt * 16;
                float2 p0 = *(const float2*)&fs[aS + (rr    ) * 40 + kb + 2 * kq];
                float2 p1 = *(const float2*)&fs[aS + (rr + 8) * 40 + kb + 2 * kq];
                float2 p2 = *(const float2*)&fs[aS + (rr    ) * 40 + kb + 2 * kq + 8];
                float2 p3 = *(const float2*)&fs[aS + (rr + 8) * 40 + kb + 2 * kq + 8];
                ah[mt][0] = pkbf(p0.x, p0.y);
                ah[mt][1] = pkbf(p1.x, p1.y);
                ah[mt][2] = pkbf(p2.x, p2.y);
                ah[mt][3] = pkbf(p3.x, p3.y);
                al[mt][0] = pkbf(p0.x - bflo(ah[mt][0]), p0.y - bfhi(ah[mt][0]));
                al[mt][1] = pkbf(p1.x - bflo(ah[mt][1]), p1.y - bfhi(ah[mt][1]));
                al[mt][2] = pkbf(p2.x - bflo(ah[mt][2]), p2.y - bfhi(ah[mt][2]));
                al[mt][3] = pkbf(p3.x - bflo(ah[mt][3]), p3.y - bfhi(ah[mt][3]));
            }
#pragma unroll
            for (int nt = 0; nt < 8; nt++) {
                int cc = cl + nt * 8;
                uint32_t bh2[2] = { us[bhS + (ks * 8 + kq    ) * 136 + cc],
                                    us[bhS + (ks * 8 + kq + 4) * 136 + cc] };
                uint32_t bl2[2] = { us[blS + (ks * 8 + kq    ) * 136 + cc],
                                    us[blS + (ks * 8 + kq + 4) * 136 + cc] };
#pragma unroll
                for (int mt = 0; mt < 2; mt++) {
                    mmabf(acc[mt][nt], ah[mt], bl2);
                    mmabf(acc[mt][nt], al[mt], bh2);
                    mmabf(acc[mt][nt], ah[mt], bh2);
                }
            }
        }
        __syncthreads();
    }

    // ---- epilogue
#pragma unroll
    for (int mt = 0; mt < 2; mt++) {
#pragma unroll
        for (int nt = 0; nt < 8; nt++) {
            int gr = rowBase + warpM * 32 + mt * 16 + (lane >> 2);
            int gc = colBase + warpN * 64 + nt * 8 + 2 * (lane & 3);
#pragma unroll
            for (int h = 0; h < 2; h++) {
                float v0 = acc[mt][nt][2 * h];
                float v1 = acc[mt][nt][2 * h + 1];
                int r = gr + h * 8;
                if (MODE == 2) {
                    float2 a2 = *reinterpret_cast<const float2*>(aux + (size_t)r * N + gc);
                    v0 *= a2.x; v1 *= a2.y;
                }
                if (MODE == 3) {
                    atomicAdd(C0 + (size_t)r * N + gc,     v0);
                    atomicAdd(C0 + (size_t)r * N + gc + 1, v1);
                } else {
                    float2 o; o.x = v0; o.y = v1;
                    *reinterpret_cast<float2*>(C0 + (size_t)r * N + gc) = o;
                }
            }
        }
    }
}

// ---------------- softplus -> A_bar -----------------------------------------
__global__ __launch_bounds__(256)
void softplus_kernel(const float* __restrict__ A_log)
{
    int m = blockIdx.x * 256 + threadIdx.x;
    float v = g_dsum[m];
    float sp = (v > 20.0f) ? v : log1pf(expf(v));
    g_a[m] = expf(-expf(A_log[0]) * sp);
}

// ---------------- parallel scan: 3 passes -----------------------------------
__global__ __launch_bounds__(128)
void prod_kernel()
{
    float v = g_a[blockIdx.x * 128 + threadIdx.x];
#pragma unroll
    for (int o = 16; o; o >>= 1) v *= __shfl_xor_sync(0xFFFFFFFFu, v, o);
    __shared__ float red[4];
    if ((threadIdx.x & 31) == 0) red[threadIdx.x >> 5] = v;
    __syncthreads();
    if (threadIdx.x == 0)
        g_prodA[blockIdx.x] = red[0] * red[1] * red[2] * red[3];
}

__global__ __launch_bounds__(256)
void scanA_kernel()
{
    int b = blockIdx.x >> 4, c = blockIdx.x & 15;
    int d = blockIdx.y * 256 + threadIdx.x;
    int s0 = c * CHLEN;
    float h = 0.0f;
    size_t base = ((size_t)b * SEQ + s0) * DINNER + d;
    int arow = b * SEQ + s0;
#pragma unroll 4
    for (int i = 0; i < CHLEN; i++)
        h = fmaf(g_a[arow + i], h, g_bx[base + (size_t)i * DINNER]);
    g_hend[(size_t)(b * NCH + c) * DINNER + d] = h;
}

__global__ __launch_bounds__(256)
void scanB_kernel()
{
    int b = blockIdx.x >> 3;
    int d = (blockIdx.x & 7) * 256 + threadIdx.x;
    float carry = 0.0f;
#pragma unroll
    for (int c = 0; c < NCH; c++) {
        size_t idx = (size_t)(b * NCH + c) * DINNER + d;
        g_carry[idx] = carry;
        carry = g_hend[idx] + g_prodA[b * NCH + c] * carry;
    }
}

// re-scan + y = tf32((C*h + D*xi)*silu(z))
__global__ __launch_bounds__(256)
void scanC_kernel(const float* __restrict__ D)
{
    int b = blockIdx.x >> 4, c = blockIdx.x & 15;
    int d = blockIdx.y * 256 + threadIdx.x;
    int s0 = c * CHLEN;
    float Dd = D[d];
    float h = g_carry[(size_t)(b * NCH + c) * DINNER + d];
    size_t base = ((size_t)b * SEQ + s0) * DINNER + d;
    int arow = b * SEQ + s0;
#pragma unroll 4
    for (int i = 0; i < CHLEN; i++) {
        size_t idx = base + (size_t)i * DINNER;
        float xi = g_xi[idx];
        h = fmaf(g_a[arow + i], h, g_bx[idx]);
        float y = fmaf(g_Cm[idx], h, Dd * xi);
        g_y[idx] = tf32r(y * g_sz[idx]);
    }
}

// ---------------- launch ----------------------------------------------------
extern "C" void kernel_launch(void* const* d_in, const int* in_sizes, int n_in,
                              void* d_out, int out_size)
{
    const float* x     = (const float*)d_in[0];
    const float* W_in  = (const float*)d_in[1];
    const float* W_xp  = (const float*)d_in[2];
    const float* W_B   = (const float*)d_in[3];
    const float* W_C   = (const float*)d_in[4];
    const float* W_out = (const float*)d_in[5];
    const float* Dvec  = (const float*)d_in[6];
    const float* A_log = (const float*)d_in[7];
    float* out = (float*)d_out;

    float *p_xi, *p_sz, *p_bx, *p_Cm, *p_y, *p_pBC, *p_dsum, *p_xr, *p_Wr, *p_Wor;
    uint32_t *p_WxhP, *p_WxlP, *p_WBhP, *p_WBlP, *p_WChP, *p_WClP;
    cudaGetSymbolAddress((void**)&p_xi,   g_xi);
    cudaGetSymbolAddress((void**)&p_sz,   g_sz);
    cudaGetSymbolAddress((void**)&p_bx,   g_bx);
    cudaGetSymbolAddress((void**)&p_Cm,   g_Cm);
    cudaGetSymbolAddress((void**)&p_y,    g_y);
    cudaGetSymbolAddress((void**)&p_pBC,  g_pBC);
    cudaGetSymbolAddress((void**)&p_dsum, g_dsum);
    cudaGetSymbolAddress((void**)&p_xr,   g_xr);
    cudaGetSymbolAddress((void**)&p_Wr,   g_Wr);
    cudaGetSymbolAddress((void**)&p_Wor,  g_Wor);
    cudaGetSymbolAddress((void**)&p_WxhP, g_WxhP);
    cudaGetSymbolAddress((void**)&p_WxlP, g_WxlP);
    cudaGetSymbolAddress((void**)&p_WBhP, g_WBhP);
    cudaGetSymbolAddress((void**)&p_WBlP, g_WBlP);
    cudaGetSymbolAddress((void**)&p_WChP, g_WChP);
    cudaGetSymbolAddress((void**)&p_WClP, g_WClP);

    cudaFuncSetAttribute(gemm_cp<0>, cudaFuncAttributeMaxDynamicSharedMemorySize, GEMM_SMEM);
    cudaFuncSetAttribute(gemm_cp<1>, cudaFuncAttributeMaxDynamicSharedMemorySize, GEMM_SMEM);
    cudaFuncSetAttribute(gemm_bf<0>, cudaFuncAttributeMaxDynamicSharedMemorySize, BF_SMEM);
    cudaFuncSetAttribute(gemm_bf<2>, cudaFuncAttributeMaxDynamicSharedMemorySize, BF_SMEM);
    cudaFuncSetAttribute(gemm_bf<3>, cudaFuncAttributeMaxDynamicSharedMemorySize, BF_SMEM);

    // ---- stream fork/join orchestration (capture-legal pattern) ----
    cudaStream_t s1, s2;
    cudaStreamCreateWithFlags(&s1, cudaStreamNonBlocking);
    cudaStreamCreateWithFlags(&s2, cudaStreamNonBlocking);
    cudaEvent_t eF, eJ1, eJ2, eFk, eCm;
    cudaEventCreateWithFlags(&eF,  cudaEventDisableTiming);
    cudaEventCreateWithFlags(&eJ1, cudaEventDisableTiming);
    cudaEventCreateWithFlags(&eJ2, cudaEventDisableTiming);
    cudaEventCreateWithFlags(&eFk, cudaEventDisableTiming);
    cudaEventCreateWithFlags(&eCm, cudaEventDisableTiming);

    // fork s1/s2 off the main (capture) stream
    cudaEventRecord(eF, 0);
    cudaStreamWaitEvent(s1, eF, 0);
    cudaStreamWaitEvent(s2, eF, 0);

    // 0) prep, distributed:
    //    main: round(x), memset(dsum)  [gemm1 deps]
    //    s1:   round(W_in)             [gemm1 dep]
    //    s2:   round(W_out), packW(B), packW(C), packxp, memset(pBC)
    round_kernel<<<MROWS * DMODEL / 1024, 256, 0, 0>>>(x, p_xr, MROWS * DMODEL / 4);
    cudaMemsetAsync(p_dsum, 0, (size_t)MROWS * sizeof(float), 0);
    round_kernel<<<DMODEL * 2 * DINNER / 1024, 256, 0, s1>>>(W_in, p_Wr, DMODEL * 2 * DINNER / 4);
    round_kernel<<<DINNER * DMODEL / 1024, 256, 0, s2>>>(W_out, p_Wor, DINNER * DMODEL / 4);
    packW_kernel<<<(DSTATE / 2) * DINNER / 256, 256, 0, s2>>>(W_B, p_WBhP, p_WBlP);
    packW_kernel<<<(DSTATE / 2) * DINNER / 256, 256, 0, s2>>>(W_C, p_WChP, p_WClP);
    packxp_kernel<<<(DINNER / 2) * 128 / 256, 256, 0, s2>>>(W_xp);
    cudaMemsetAsync(p_pBC, 0, (size_t)MROWS * 128 * sizeof(float), s2);

    // join s1 (W_in) before gemm1
    cudaEventRecord(eJ1, s1);
    cudaStreamWaitEvent(0, eJ1, 0);

    // 1) xz = x @ W_in -> xi, silu(z); fused delta dot -> g_dsum
    gemm_cp<1><<<dim3(32, 64), 256, GEMM_SMEM, 0>>>(
        p_xr, DMODEL, p_Wr, 2 * DINNER, p_xi, p_sz, W_xp, 2 * DINNER, DMODEL);

    // 2) softplus -> A_bar; chunk products
    softplus_kernel<<<MROWS / 256, 256, 0, 0>>>(A_log);
    prod_kernel<<<BATCH * NCH, 128, 0, 0>>>();

    // join s2 (packs + pBC memset) before projBC
    cudaEventRecord(eJ2, s2);
    cudaStreamWaitEvent(0, eJ2, 0);

    // 3) [B_raw|C_raw] = xi @ W_xp[:,1:129]  (split-K x8, 2-term bf16)
    gemm_bf<3><<<dim3(1, 64, 8), 256, BF_SMEM, 0>>>(
        p_xi, DINNER, p_WxhP, p_WxlP, 128, p_pBC, nullptr, 128, DINNER / 8);

    // fork: Cm GEMM on s1, concurrent with bx GEMM + scanA + scanB on main
    cudaEventRecord(eFk, 0);
    cudaStreamWaitEvent(s1, eFk, 0);

    // 5') Cm = C_raw @ W_C  (2-term bf16)  — on s1
    gemm_bf<0><<<dim3(16, 64), 256, BF_SMEM, s1>>>(
        p_pBC + 64, 128, p_WChP, p_WClP, DINNER, p_Cm, nullptr, DINNER, DSTATE);

    // 4) bx = (B_raw @ W_B) * xi  (2-term bf16)  — on main
    gemm_bf<2><<<dim3(16, 64), 256, BF_SMEM, 0>>>(
        p_pBC, 128, p_WBhP, p_WBlP, DINNER, p_bx, p_xi, DINNER, DSTATE);

    // 6) scan passes A, B on main
    scanA_kernel<<<dim3(BATCH * NCH, DINNER / 256), 256, 0, 0>>>();
    scanB_kernel<<<BATCH * (DINNER / 256), 256, 0, 0>>>();

    // join Cm before scanC
    cudaEventRecord(eCm, s1);
    cudaStreamWaitEvent(0, eCm, 0);

    scanC_kernel<<<dim3(BATCH * NCH, DINNER / 256), 256, 0, 0>>>(Dvec);

    // 7) out = y @ W_out
    gemm_cp<0><<<dim3(8, 64), 256, GEMM_SMEM, 0>>>(
        p_y, DINNER, p_Wor, DMODEL, out, nullptr, nullptr, DMODEL, DINNER);

    cudaEventDestroy(eF);  cudaEventDestroy(eJ1); cudaEventDestroy(eJ2);
    cudaEventDestroy(eFk); cudaEventDestroy(eCm);
    cudaStreamDestroy(s1); cudaStreamDestroy(s2);
}

// round 15
// speedup vs baseline: 1.2451x; 1.0093x over previous
#include <cuda_runtime.h>
#include <cstdint>
#include <math.h>

#define BATCH   4
#define SEQ     2048
#define DMODEL  1024
#define DINNER  2048
#define DSTATE  64
#define MROWS   (BATCH*SEQ)      /* 8192 */
#define NPROJ   (2*DSTATE+1)     /* 129  */
#define NCH     16               /* scan chunks */
#define CHLEN   (SEQ/NCH)        /* 128 */

// ---------------- scratch (device globals; no allocations allowed) ----------
__device__ float g_xi  [MROWS*DINNER];
__device__ float g_sz  [MROWS*DINNER];
__device__ float g_bx  [MROWS*DINNER];
__device__ float g_Cm  [MROWS*DINNER];
__device__ float g_y   [MROWS*DINNER];
__device__ float g_pBC [MROWS*128];
__device__ float g_dsum[MROWS];
__device__ float g_a   [MROWS];
__device__ float g_hend [BATCH*NCH*DINNER];
__device__ float g_carry[BATCH*NCH*DINNER];
__device__ float g_prodA[BATCH*NCH];
__device__ float g_xr  [MROWS*DMODEL];      // rounded x
__device__ float g_Wr  [DMODEL*2*DINNER];   // rounded W_in
__device__ float g_Wor [DINNER*DMODEL];     // rounded W_out
__device__ uint32_t g_WxhP[(DINNER/2)*128]; // W_xp[:,1:] k-pair bf16x2 hi
__device__ uint32_t g_WxlP[(DINNER/2)*128]; //                          lo
__device__ uint32_t g_WBhP[(DSTATE/2)*DINNER];
__device__ uint32_t g_WBlP[(DSTATE/2)*DINNER];
__device__ uint32_t g_WChP[(DSTATE/2)*DINNER];
__device__ uint32_t g_WClP[(DSTATE/2)*DINNER];

// ---------------- helpers ---------------------------------------------------
__device__ __forceinline__ uint32_t smem_u32(const void* p) {
    uint32_t a;
    asm("{ .reg .u64 t; cvta.to.shared.u64 t, %1; cvt.u32.u64 %0, t; }" : "=r"(a) : "l"(p));
    return a;
}
__device__ __forceinline__ float tf32r(float x) {
    float y; asm("cvt.rna.tf32.f32 %0, %1;" : "=f"(y) : "f"(x)); return y;
}
__device__ __forceinline__ uint32_t pkbf(float lo, float hi) {
    uint32_t r; asm("cvt.rn.bf16x2.f32 %0, %1, %2;" : "=r"(r) : "f"(hi), "f"(lo)); return r;
}
__device__ __forceinline__ float bflo(uint32_t p) { return __uint_as_float(p << 16); }
__device__ __forceinline__ float bfhi(uint32_t p) { return __uint_as_float(p & 0xFFFF0000u); }

__device__ __forceinline__ void cp16(uint32_t s, const void* g) {
    asm volatile("cp.async.cg.shared.global [%0], [%1], 16;" :: "r"(s), "l"(g));
}
#define CP_COMMIT asm volatile("cp.async.commit_group;" ::: "memory")
#define CP_WAIT1  asm volatile("cp.async.wait_group 1;" ::: "memory")
#define CP_WAIT0  asm volatile("cp.async.wait_group 0;" ::: "memory")

__device__ __forceinline__ void mma8(float* c, const uint32_t* a, const uint32_t* b) {
    asm volatile(
        "mma.sync.aligned.m16n8k8.row.col.f32.tf32.tf32.f32 "
        "{%0,%1,%2,%3}, {%4,%5,%6,%7}, {%8,%9}, {%0,%1,%2,%3};"
        : "+f"(c[0]), "+f"(c[1]), "+f"(c[2]), "+f"(c[3])
        : "r"(a[0]), "r"(a[1]), "r"(a[2]), "r"(a[3]), "r"(b[0]), "r"(b[1]));
}
__device__ __forceinline__ void mmabf(float* c, const uint32_t* a, const uint32_t* b) {
    asm volatile(
        "mma.sync.aligned.m16n8k16.row.col.f32.bf16.bf16.f32 "
        "{%0,%1,%2,%3}, {%4,%5,%6,%7}, {%8,%9}, {%0,%1,%2,%3};"
        : "+f"(c[0]), "+f"(c[1]), "+f"(c[2]), "+f"(c[3])
        : "r"(a[0]), "r"(a[1]), "r"(a[2]), "r"(a[3]), "r"(b[0]), "r"(b[1]));
}

// ---------------- prep kernels ----------------------------------------------
__global__ __launch_bounds__(256)
void round_kernel(const float* __restrict__ src, float* __restrict__ dst, int n4)
{
    int i = blockIdx.x * 256 + threadIdx.x;
    if (i < n4) {
        float4 v = reinterpret_cast<const float4*>(src)[i];
        v.x = tf32r(v.x); v.y = tf32r(v.y); v.z = tf32r(v.z); v.w = tf32r(v.w);
        reinterpret_cast<float4*>(dst)[i] = v;
    }
}

// W_B / W_C -> k-pair bf16x2 hi/lo [DSTATE/2][DINNER]
__global__ __launch_bounds__(256)
void packW_kernel(const float* __restrict__ src, uint32_t* __restrict__ dh,
                  uint32_t* __restrict__ dl)
{
    int i = blockIdx.x * 256 + threadIdx.x;
    int kp = i >> 11, n = i & 2047;
    float v0 = src[(size_t)(2 * kp) * DINNER + n];
    float v1 = src[(size_t)(2 * kp + 1) * DINNER + n];
    uint32_t h = pkbf(v0, v1);
    dh[i] = h;
    dl[i] = pkbf(v0 - bflo(h), v1 - bfhi(h));
}

// W_xp[:,1:129] -> k-pair bf16x2 hi/lo [DINNER/2][128]
__global__ __launch_bounds__(256)
void packxp_kernel(const float* __restrict__ W)
{
    int i = blockIdx.x * 256 + threadIdx.x;
    int kp = i >> 7, n = i & 127;
    float v0 = W[(size_t)(2 * kp) * NPROJ + 1 + n];
    float v1 = W[(size_t)(2 * kp + 1) * NPROJ + 1 + n];
    uint32_t h = pkbf(v0, v1);
    g_WxhP[i] = h;
    g_WxlP[i] = pkbf(v0 - bflo(h), v1 - bfhi(h));
}

// ======================= tf32 mma.sync GEMM, cp.async 3-stage ===============
// A and B both pre-rounded to tf32 (NO cvt in mainloop). Single sync per iter.
// MODE 0: C0=v   MODE 1: split xi / silu(z), fused delta dot into g_dsum
#define STG_SZ  35840u     /* 18432 A + 17408 B per stage */
#define GEMM_SMEM 107520   /* 3 stages */

template <int MODE>
__global__ void __launch_bounds__(256, 2)
gemm_cp(const float* __restrict__ A, int lda,
        const float* __restrict__ B, int ldb,
        float* __restrict__ C0, float* __restrict__ C1,
        const float* __restrict__ wxp,
        int N, int K)
{
    extern __shared__ char smem[];
    const uint32_t sbase = smem_u32(smem);
    float* fs = (float*)smem;

    const int t    = threadIdx.x;
    const int lane = t & 31;
    const int wid  = t >> 5;
    const int warpM = wid & 3;
    const int warpN = wid >> 2;

    int bx = blockIdx.x, by = blockIdx.y;
    {
        int lin = by * gridDim.x + bx;
        int per = gridDim.x * 8;
        int p = lin / per, rem = lin % per;
        by = p * 8 + (rem & 7);
        bx = rem >> 3;
    }
    const int rowBase = by * 128;
    const int colBase = bx * 128;

    float acc[2][8][4];
#pragma unroll
    for (int i = 0; i < 2; i++)
#pragma unroll
        for (int j = 0; j < 8; j++)
#pragma unroll
            for (int q = 0; q < 4; q++) acc[i][j][q] = 0.0f;

    const int nkt = K / 32;

    auto issue = [&](int st, int kt) {
        const int k0 = kt * 32;
        const uint32_t sA = sbase + (uint32_t)st * STG_SZ;
        const uint32_t sB = sA + 18432u;
#pragma unroll
        for (int e = 0; e < 4; e++) {
            int id = t + 256 * e;
            int r = id >> 3, q = id & 7;
            cp16(sA + (uint32_t)(r * 36 + q * 4) * 4,
                 A + (size_t)(rowBase + r) * lda + k0 + q * 4);
        }
#pragma unroll
        for (int e = 0; e < 4; e++) {
            int id = t + 256 * e;
            int k = id >> 5, q = id & 31;
            cp16(sB + (uint32_t)(k * 136 + q * 4) * 4,
                 B + (size_t)(k0 + k) * ldb + colBase + q * 4);
        }
    };

    issue(0, 0);
    CP_COMMIT;
    if (nkt > 1) { issue(1, 1); CP_COMMIT; }

    const int r0 = warpM * 32 + (lane >> 2);
    const int kq = lane & 3;
    const int cl = warpN * 64 + (lane >> 2);

    for (int kt = 0; kt < nkt; kt++) {
        if (kt + 1 < nkt) CP_WAIT1; else CP_WAIT0;
        __syncthreads();
        if (kt + 2 < nkt) { issue((kt + 2) % 3, kt + 2); CP_COMMIT; }

        const uint32_t aS = (uint32_t)(kt % 3) * (STG_SZ / 4);
        const uint32_t bS = aS + 18432 / 4;
#pragma unroll
        for (int ks = 0; ks < 4; ks++) {
            const int kb = ks * 8;
            uint32_t af[2][4];
#pragma unroll
            for (int mt = 0; mt < 2; mt++) {
                int rr = r0 + mt * 16;
                af[mt][0] = __float_as_uint(fs[aS + (rr    ) * 36 + kb + kq]);
                af[mt][1] = __float_as_uint(fs[aS + (rr + 8) * 36 + kb + kq]);
                af[mt][2] = __float_as_uint(fs[aS + (rr    ) * 36 + kb + kq + 4]);
                af[mt][3] = __float_as_uint(fs[aS + (rr + 8) * 36 + kb + kq + 4]);
            }
#pragma unroll
            for (int nt = 0; nt < 8; nt++) {
                int cc = cl + nt * 8;
                uint32_t bf[2] = {
                    __float_as_uint(fs[bS + (kb + kq    ) * 136 + cc]),
                    __float_as_uint(fs[bS + (kb + kq + 4) * 136 + cc]) };
#pragma unroll
                for (int mt = 0; mt < 2; mt++)
                    mma8(acc[mt][nt], af[mt], bf);
            }
        }
    }

    // ---- epilogue
    float* C = C0;
    int cbase = colBase;
    bool do_silu = false;
    int cstride = N;
    if (MODE == 1) {
        cstride = DINNER;
        if (colBase >= DINNER) { C = C1; cbase = colBase - DINNER; do_silu = true; }
    }

    float ds[4] = {0.0f, 0.0f, 0.0f, 0.0f};

#pragma unroll
    for (int mt = 0; mt < 2; mt++) {
#pragma unroll
        for (int nt = 0; nt < 8; nt++) {
            int gr = rowBase + warpM * 32 + mt * 16 + (lane >> 2);
            int gc = cbase + warpN * 64 + nt * 8 + 2 * (lane & 3);
            float w0a = 0.0f, w0b = 0.0f;
            if (MODE == 1 && !do_silu) {
                w0a = __ldg(&wxp[(size_t)gc * NPROJ]);
                w0b = __ldg(&wxp[(size_t)(gc + 1) * NPROJ]);
            }
#pragma unroll
            for (int h = 0; h < 2; h++) {
                float v0 = acc[mt][nt][2 * h];
                float v1 = acc[mt][nt][2 * h + 1];
                int r = gr + h * 8;
                if (MODE == 1) {
                    if (do_silu) {
                        v0 = v0 / (1.0f + expf(-v0));
                        v1 = v1 / (1.0f + expf(-v1));
                    } else {
                        ds[mt * 2 + h] += v0 * w0a + v1 * w0b;
                    }
                }
                float2 o; o.x = v0; o.y = v1;
                *reinterpret_cast<float2*>(C + (size_t)r * cstride + gc) = o;
            }
        }
    }

    if (MODE == 1 && !do_silu) {
#pragma unroll
        for (int i = 0; i < 4; i++) {
            float v = ds[i];
            v += __shfl_xor_sync(0xFFFFFFFFu, v, 1);
            v += __shfl_xor_sync(0xFFFFFFFFu, v, 2);
            if ((lane & 3) == 0) {
                int r = rowBase + warpM * 32 + (i >> 1) * 16 + (i & 1) * 8 + (lane >> 2);
                atomicAdd(&g_dsum[r], v);
            }
        }
    }
}

// ============ 2-term bf16 split GEMM (m16n8k16), prebuilt hi/lo B ===========
// 3 MMAs per K=16: ah*bh + ah*bl + al*bh  (al*bl ~ 2^-18, dropped).
// MODE 0: C0=v   MODE 2: C0=v*aux   MODE 3: atomicAdd (split-K)
#define BF_STG  37888u     /* 20480 A + 8704 Bh + 8704 Bl */
#define BF_SMEM 75776

template <int MODE>
__global__ void __launch_bounds__(256, 2)
gemm_bf(const float* __restrict__ A, int lda,
        const uint32_t* __restrict__ Bh, const uint32_t* __restrict__ Bl, int ldbp,
        float* __restrict__ C0, const float* __restrict__ aux,
        int N, int K)
{
    extern __shared__ char smem[];
    const uint32_t sbase = smem_u32(smem);
    float* fs = (float*)smem;
    uint32_t* us = (uint32_t*)smem;

    const int t    = threadIdx.x;
    const int lane = t & 31;
    const int wid  = t >> 5;
    const int warpM = wid & 3;
    const int warpN = wid >> 2;
    const int rowBase = blockIdx.y * 128;
    const int colBase = blockIdx.x * 128;
    const int kBase   = blockIdx.z * K;

    float acc[2][8][4];
#pragma unroll
    for (int i = 0; i < 2; i++)
#pragma unroll
        for (int j = 0; j < 8; j++)
#pragma unroll
            for (int q = 0; q < 4; q++) acc[i][j][q] = 0.0f;

    const int nkt = K / 32;

    auto issue = [&](int st, int kt) {
        const int k0  = kBase + kt * 32;
        const int k0p = k0 >> 1;
        const uint32_t sA  = sbase + (uint32_t)st * BF_STG;
        const uint32_t sBh = sA + 20480u;
        const uint32_t sBl = sBh + 8704u;
#pragma unroll
        for (int e = 0; e < 4; e++) {
            int id = t + 256 * e;
            int r = id >> 3, q = id & 7;
            cp16(sA + (uint32_t)(r * 40 + q * 4) * 4,
                 A + (size_t)(rowBase + r) * lda + k0 + q * 4);
        }
#pragma unroll
        for (int e = 0; e < 2; e++) {
            int id = t + 256 * e;
            int kp = id >> 5, q = id & 31;
            cp16(sBh + (uint32_t)(kp * 136 + q * 4) * 4,
                 Bh + (size_t)(k0p + kp) * ldbp + colBase + q * 4);
            cp16(sBl + (uint32_t)(kp * 136 + q * 4) * 4,
                 Bl + (size_t)(k0p + kp) * ldbp + colBase + q * 4);
        }
    };

    issue(0, 0);
    CP_COMMIT;

    const int r0 = warpM * 32 + (lane >> 2);
    const int kq = lane & 3;
    const int cl = warpN * 64 + (lane >> 2);

    for (int kt = 0; kt < nkt; kt++) {
        if (kt + 1 < nkt) { issue((kt + 1) & 1, kt + 1); CP_COMMIT; CP_WAIT1; }
        else              { CP_WAIT0; }
        __syncthreads();

        const uint32_t aS  = (uint32_t)(kt & 1) * (BF_STG / 4);
        const uint32_t bhS = aS + 20480 / 4;
        const uint32_t blS = bhS + 8704 / 4;
#pragma unroll
        for (int ks = 0; ks < 2; ks++) {
            const int kb = ks * 16;
            uint32_t ah[2][4], al[2][4];
#pragma unroll
            for (int mt = 0; mt < 2; mt++) {
                int rr = r0 + mt * 16;
                float2 p0 = *(const float2*)&fs[aS + (rr    ) * 40 + kb + 2 * kq];
                float2 p1 = *(const float2*)&fs[aS + (rr + 8) * 40 + kb + 2 * kq];
                float2 p2 = *(const float2*)&fs[aS + (rr    ) * 40 + kb + 2 * kq + 8];
                float2 p3 = *(const float2*)&fs[aS + (rr + 8) * 40 + kb + 2 * kq + 8];
                ah[mt][0] = pkbf(p0.x, p0.y);
                ah[mt][1] = pkbf(p1.x, p1.y);
                ah[mt][2] = pkbf(p2.x, p2.y);
                ah[mt][3] = pkbf(p3.x, p3.y);
                al[mt][0] = pkbf(p0.x - bflo(ah[mt][0]), p0.y - bfhi(ah[mt][0]));
                al[mt][1] = pkbf(p1.x - bflo(ah[mt][1]), p1.y - bfhi(ah[mt][1]));
                al[mt][2] = pkbf(p2.x - bflo(ah[mt][2]), p2.y - bfhi(ah[mt][2]));
                al[mt][3] = pkbf(p3.x - bflo(ah[mt][3]), p3.y - bfhi(ah[mt][3]));
            }
#pragma unroll
            for (int nt = 0; nt < 8; nt++) {
                int cc = cl + nt * 8;
                uint32_t bh2[2] = { us[bhS + (ks * 8 + kq    ) * 136 + cc],
                                    us[bhS + (ks * 8 + kq + 4) * 136 + cc] };
                uint32_t bl2[2] = { us[blS + (ks * 8 + kq    ) * 136 + cc],
                                    us[blS + (ks * 8 + kq + 4) * 136 + cc] };
#pragma unroll
                for (int mt = 0; mt < 2; mt++) {
                    mmabf(acc[mt][nt], ah[mt], bl2);
                    mmabf(acc[mt][nt], al[mt], bh2);
                    mmabf(acc[mt][nt], ah[mt], bh2);
                }
            }
        }
        __syncthreads();
    }

    // ---- epilogue
#pragma unroll
    for (int mt = 0; mt < 2; mt++) {
#pragma unroll
        for (int nt = 0; nt < 8; nt++) {
            int gr = rowBase + warpM * 32 + mt * 16 + (lane >> 2);
            int gc = colBase + warpN * 64 + nt * 8 + 2 * (lane & 3);
#pragma unroll
            for (int h = 0; h < 2; h++) {
                float v0 = acc[mt][nt][2 * h];
                float v1 = acc[mt][nt][2 * h + 1];
                int r = gr + h * 8;
                if (MODE == 2) {
                    float2 a2 = *reinterpret_cast<const float2*>(aux + (size_t)r * N + gc);
                    v0 *= a2.x; v1 *= a2.y;
                }
                if (MODE == 3) {
                    atomicAdd(C0 + (size_t)r * N + gc,     v0);
                    atomicAdd(C0 + (size_t)r * N + gc + 1, v1);
                } else {
                    float2 o; o.x = v0; o.y = v1;
                    *reinterpret_cast<float2*>(C0 + (size_t)r * N + gc) = o;
                }
            }
        }
    }
}

// ---------------- softplus -> A_bar + chunk products (merged) ---------------
__global__ __launch_bounds__(128)
void softprod_kernel(const float* __restrict__ A_log)
{
    int m = blockIdx.x * 128 + threadIdx.x;
    float v = g_dsum[m];
    float sp = (v > 20.0f) ? v : log1pf(expf(v));
    float a = expf(-expf(A_log[0]) * sp);
    g_a[m] = a;
    float p = a;
#pragma unroll
    for (int o = 16; o; o >>= 1) p *= __shfl_xor_sync(0xFFFFFFFFu, p, o);
    __shared__ float red[4];
    if ((threadIdx.x & 31) == 0) red[threadIdx.x >> 5] = p;
    __syncthreads();
    if (threadIdx.x == 0)
        g_prodA[blockIdx.x] = red[0] * red[1] * red[2] * red[3];
}

// ---------------- parallel scan: 3 passes -----------------------------------
__global__ __launch_bounds__(256)
void scanA_kernel()
{
    int b = blockIdx.x >> 4, c = blockIdx.x & 15;
    int d = blockIdx.y * 256 + threadIdx.x;
    int s0 = c * CHLEN;
    float h = 0.0f;
    size_t base = ((size_t)b * SEQ + s0) * DINNER + d;
    int arow = b * SEQ + s0;
#pragma unroll 4
    for (int i = 0; i < CHLEN; i++)
        h = fmaf(g_a[arow + i], h, g_bx[base + (size_t)i * DINNER]);
    g_hend[(size_t)(b * NCH + c) * DINNER + d] = h;
}

__global__ __launch_bounds__(256)
void scanB_kernel()
{
    int b = blockIdx.x >> 3;
    int d = (blockIdx.x & 7) * 256 + threadIdx.x;
    float carry = 0.0f;
#pragma unroll
    for (int c = 0; c < NCH; c++) {
        size_t idx = (size_t)(b * NCH + c) * DINNER + d;
        g_carry[idx] = carry;
        carry = g_hend[idx] + g_prodA[b * NCH + c] * carry;
    }
}

// re-scan + y = tf32((C*h + D*xi)*silu(z))
__global__ __launch_bounds__(256)
void scanC_kernel(const float* __restrict__ D)
{
    int b = blockIdx.x >> 4, c = blockIdx.x & 15;
    int d = blockIdx.y * 256 + threadIdx.x;
    int s0 = c * CHLEN;
    float Dd = D[d];
    float h = g_carry[(size_t)(b * NCH + c) * DINNER + d];
    size_t base = ((size_t)b * SEQ + s0) * DINNER + d;
    int arow = b * SEQ + s0;
#pragma unroll 4
    for (int i = 0; i < CHLEN; i++) {
        size_t idx = base + (size_t)i * DINNER;
        float xi = g_xi[idx];
        h = fmaf(g_a[arow + i], h, g_bx[idx]);
        float y = fmaf(g_Cm[idx], h, Dd * xi);
        g_y[idx] = tf32r(y * g_sz[idx]);
    }
}

// ---------------- launch ----------------------------------------------------
extern "C" void kernel_launch(void* const* d_in, const int* in_sizes, int n_in,
                              void* d_out, int out_size)
{
    const float* x     = (const float*)d_in[0];
    const float* W_in  = (const float*)d_in[1];
    const float* W_xp  = (const float*)d_in[2];
    const float* W_B   = (const float*)d_in[3];
    const float* W_C   = (const float*)d_in[4];
    const float* W_out = (const float*)d_in[5];
    const float* Dvec  = (const float*)d_in[6];
    const float* A_log = (const float*)d_in[7];
    float* out = (float*)d_out;

    float *p_xi, *p_sz, *p_bx, *p_Cm, *p_y, *p_pBC, *p_dsum, *p_xr, *p_Wr, *p_Wor;
    uint32_t *p_WxhP, *p_WxlP, *p_WBhP, *p_WBlP, *p_WChP, *p_WClP;
    cudaGetSymbolAddress((void**)&p_xi,   g_xi);
    cudaGetSymbolAddress((void**)&p_sz,   g_sz);
    cudaGetSymbolAddress((void**)&p_bx,   g_bx);
    cudaGetSymbolAddress((void**)&p_Cm,   g_Cm);
    cudaGetSymbolAddress((void**)&p_y,    g_y);
    cudaGetSymbolAddress((void**)&p_pBC,  g_pBC);
    cudaGetSymbolAddress((void**)&p_dsum, g_dsum);
    cudaGetSymbolAddress((void**)&p_xr,   g_xr);
    cudaGetSymbolAddress((void**)&p_Wr,   g_Wr);
    cudaGetSymbolAddress((void**)&p_Wor,  g_Wor);
    cudaGetSymbolAddress((void**)&p_WxhP, g_WxhP);
    cudaGetSymbolAddress((void**)&p_WxlP, g_WxlP);
    cudaGetSymbolAddress((void**)&p_WBhP, g_WBhP);
    cudaGetSymbolAddress((void**)&p_WBlP, g_WBlP);
    cudaGetSymbolAddress((void**)&p_WChP, g_WChP);
    cudaGetSymbolAddress((void**)&p_WClP, g_WClP);

    cudaFuncSetAttribute(gemm_cp<0>, cudaFuncAttributeMaxDynamicSharedMemorySize, GEMM_SMEM);
    cudaFuncSetAttribute(gemm_cp<1>, cudaFuncAttributeMaxDynamicSharedMemorySize, GEMM_SMEM);
    cudaFuncSetAttribute(gemm_bf<0>, cudaFuncAttributeMaxDynamicSharedMemorySize, BF_SMEM);
    cudaFuncSetAttribute(gemm_bf<2>, cudaFuncAttributeMaxDynamicSharedMemorySize, BF_SMEM);
    cudaFuncSetAttribute(gemm_bf<3>, cudaFuncAttributeMaxDynamicSharedMemorySize, BF_SMEM);

    // ---- stream fork/join orchestration (capture-legal pattern) ----
    cudaStream_t s1, s2;
    cudaStreamCreateWithFlags(&s1, cudaStreamNonBlocking);
    cudaStreamCreateWithFlags(&s2, cudaStreamNonBlocking);
    cudaEvent_t eF, eJ1, eJ2, eW, eG1, eSP, eFk, eCm;
    cudaEventCreateWithFlags(&eF,  cudaEventDisableTiming);
    cudaEventCreateWithFlags(&eJ1, cudaEventDisableTiming);
    cudaEventCreateWithFlags(&eJ2, cudaEventDisableTiming);
    cudaEventCreateWithFlags(&eW,  cudaEventDisableTiming);
    cudaEventCreateWithFlags(&eG1, cudaEventDisableTiming);
    cudaEventCreateWithFlags(&eSP, cudaEventDisableTiming);
    cudaEventCreateWithFlags(&eFk, cudaEventDisableTiming);
    cudaEventCreateWithFlags(&eCm, cudaEventDisableTiming);

    // fork s1/s2 off the main (capture) stream
    cudaEventRecord(eF, 0);
    cudaStreamWaitEvent(s1, eF, 0);
    cudaStreamWaitEvent(s2, eF, 0);

    // 0) prep, distributed:
    //    main: round(x), memset(dsum)                          [gemm1 deps]
    //    s1:   round(W_in)                                     [gemm1 dep]
    //    s2:   packW(B), packW(C), packxp, memset(pBC) [projBC deps] then
    //          round(W_out) [gemm_out dep, joined late]
    round_kernel<<<MROWS * DMODEL / 1024, 256, 0, 0>>>(x, p_xr, MROWS * DMODEL / 4);
    cudaMemsetAsync(p_dsum, 0, (size_t)MROWS * sizeof(float), 0);
    round_kernel<<<DMODEL * 2 * DINNER / 1024, 256, 0, s1>>>(W_in, p_Wr, DMODEL * 2 * DINNER / 4);
    packW_kernel<<<(DSTATE / 2) * DINNER / 256, 256, 0, s2>>>(W_B, p_WBhP, p_WBlP);
    packW_kernel<<<(DSTATE / 2) * DINNER / 256, 256, 0, s2>>>(W_C, p_WChP, p_WClP);
    packxp_kernel<<<(DINNER / 2) * 128 / 256, 256, 0, s2>>>(W_xp);
    cudaMemsetAsync(p_pBC, 0, (size_t)MROWS * 128 * sizeof(float), s2);
    cudaEventRecord(eJ2, s2);                    // projBC deps ready
    round_kernel<<<DINNER * DMODEL / 1024, 256, 0, s2>>>(W_out, p_Wor, DINNER * DMODEL / 4);
    cudaEventRecord(eW, s2);                     // gemm_out weight ready

    // join s1 (W_in) before gemm1
    cudaEventRecord(eJ1, s1);
    cudaStreamWaitEvent(0, eJ1, 0);

    // 1) xz = x @ W_in -> xi, silu(z); fused delta dot -> g_dsum
    gemm_cp<1><<<dim3(32, 64), 256, GEMM_SMEM, 0>>>(
        p_xr, DMODEL, p_Wr, 2 * DINNER, p_xi, p_sz, W_xp, 2 * DINNER, DMODEL);
    cudaEventRecord(eG1, 0);

    // 2) softplus + chunk products on s1, overlapped with projBC on main
    cudaStreamWaitEvent(s1, eG1, 0);
    softprod_kernel<<<BATCH * NCH, 128, 0, s1>>>(A_log);
    cudaEventRecord(eSP, s1);

    // 3) projBC on main (needs xi + s2 packs only)
    cudaStreamWaitEvent(0, eJ2, 0);
    gemm_bf<3><<<dim3(1, 64, 8), 256, BF_SMEM, 0>>>(
        p_xi, DINNER, p_WxhP, p_WxlP, 128, p_pBC, nullptr, 128, DINNER / 8);

    // fork: Cm GEMM on s1 (after its softprod), concurrent with bx+scanA+scanB
    cudaEventRecord(eFk, 0);
    cudaStreamWaitEvent(s1, eFk, 0);
    gemm_bf<0><<<dim3(16, 64), 256, BF_SMEM, s1>>>(
        p_pBC + 64, 128, p_WChP, p_WClP, DINNER, p_Cm, nullptr, DINNER, DSTATE);
    cudaEventRecord(eCm, s1);

    // 4) bx = (B_raw @ W_B) * xi  — on main
    gemm_bf<2><<<dim3(16, 64), 256, BF_SMEM, 0>>>(
        p_pBC, 128, p_WBhP, p_WBlP, DINNER, p_bx, p_xi, DINNER, DSTATE);

    // 5) scans: A needs g_a (join softprod), B needs prodA
    cudaStreamWaitEvent(0, eSP, 0);
    scanA_kernel<<<dim3(BATCH * NCH, DINNER / 256), 256, 0, 0>>>();
    scanB_kernel<<<BATCH * (DINNER / 256), 256, 0, 0>>>();

    // join Cm before scanC
    cudaStreamWaitEvent(0, eCm, 0);
    scanC_kernel<<<dim3(BATCH * NCH, DINNER / 256), 256, 0, 0>>>(Dvec);

    // 6) out = y @ W_out (join W_out round)
    cudaStreamWaitEvent(0, eW, 0);
    gemm_cp<0><<<dim3(8, 64), 256, GEMM_SMEM, 0>>>(
        p_y, DINNER, p_Wor, DMODEL, out, nullptr, nullptr, DMODEL, DINNER);

    cudaEventDestroy(eF);  cudaEventDestroy(eJ1); cudaEventDestroy(eJ2);
    cudaEventDestroy(eW);  cudaEventDestroy(eG1); cudaEventDestroy(eSP);
    cudaEventDestroy(eFk); cudaEventDestroy(eCm);
    cudaStreamDestroy(s1); cudaStreamDestroy(s2);
}